// round 11
// baseline (speedup 1.0000x reference)
#include <cuda_runtime.h>
#include <cuda_bf16.h>

#define NCTA 128
#define TPB  512
#define FPITERS 2
#define NIN0 12
#define NIN1 8
#define MAXSWEEP 5
#define JTHR 1e-13f

// ---------------- device scratch (no allocation allowed) ----------------
__device__ __align__(16) float g_qf[4096];
__device__ __align__(16) float g_StS[4096];
__device__ __align__(16) float g_b[4096];   // rhs; later reused as M staging
__device__ __align__(16) float g_x[4096];
__device__ __align__(16) float g_y[4096];
__device__ int g_cnt = 0;
__device__ int g_gen = 0;   // monotone across graph replays; g_cnt self-resets

// device-wide barrier: replay-safe (cnt self-resets; gen only increments)
__device__ __forceinline__ void gbar() {
    __threadfence();
    __syncthreads();
    if (threadIdx.x == 0) {
        int my = *(volatile int*)&g_gen;
        int old = atomicAdd(&g_cnt, 1);
        if (old == NCTA - 1) {
            g_cnt = 0;
            __threadfence();
            atomicAdd(&g_gen, 1);
        } else {
            while (*(volatile int*)&g_gen == my) { }
        }
    }
    __syncthreads();
    __threadfence();
}

struct SolveSm {
    float Ms[64*65];      // StS (apply); Ss staging (prep)
    float xs[4096];       // matvec x cache
    float zs[2][64];      // apply double buffer
};
struct FinalSm {
    float Gf[64*68];      // column j at Gf[j*68 + r]; 17 float4s per column
    float Xs[64*65];      // pristine X; then Y = G^T X; then Z = M Y
    float nrm[64];
    float sarr[64];
    float fsc[64];
    float thr_s;
};
union __align__(16) Smem { SolveSm s; FinalSm f; };

__global__ void __launch_bounds__(TPB, 1)
k_all(const float* __restrict__ inp, const float* __restrict__ L,
      const void* __restrict__ mask, const float* __restrict__ D,
      const float* __restrict__ thP, const float* __restrict__ vp,
      const float* __restrict__ netap, const float* __restrict__ lam1p,
      const float* __restrict__ lam2p, const float* __restrict__ rhop,
      const float* __restrict__ S, float* __restrict__ out) {
    __shared__ Smem sm;
    __shared__ int s_badU8, s_off1;
    int t = threadIdx.x;
    int cta = blockIdx.x;

    // ================= phase 0: prep (CTA0), StS (CTA1-4), D L2-warm (rest) ====
    if (cta == 0) {
        if (t == 0) { s_badU8 = 0; s_off1 = 0; }
        __syncthreads();
        const unsigned char* m8 = (const unsigned char*)mask;
        int b1 = 0, b2 = 0;
        for (int i = t; i < 4096; i += TPB) {
            unsigned v = m8[i];
            if (v > 1u) b1 = 1;
            if (v == 1u && (i & 3) != 0) b2 = 1;
        }
        if (b1) s_badU8 = 1;        // benign races
        if (b2) s_off1 = 1;
        __syncthreads();
        int mode = s_badU8 ? 1 : (s_off1 ? 0 : 2);   // 0=u8,1=f32,2=i32
        float rho = *rhop;
        for (int i = t; i < 4096; i += TPB) {
            bool on;
            if (mode == 0)      on = ((const unsigned char*)mask)[i] != 0;
            else if (mode == 1) on = ((const float*)mask)[i] != 0.0f;
            else                on = ((const int*)mask)[i] != 0;
            g_qf[i] = on ? 1.0f : 0.0f;
            g_b[i]  = rho * (L[i] - thP[i]) + (on ? inp[i] : 0.0f);
        }
    } else if (cta <= 4) {
        for (int i = t; i < 4096; i += TPB) { int h = i >> 6, a = i & 63; sm.s.Ms[h*65 + a] = S[i]; }
        __syncthreads();
        int base = (cta - 1) * 1024;
        #pragma unroll
        for (int k = 0; k < 2; k++) {
            int idx = base + t + k*TPB;
            int a = idx >> 6, b = idx & 63;
            float acc = 0.0f;
            #pragma unroll 16
            for (int h = 0; h < 64; h++) acc += sm.s.Ms[h*65 + a] * sm.s.Ms[h*65 + b];
            g_StS[idx] = acc;
        }
    } else {
        // warm D into L2 (sink into g_y; fully overwritten by first matvec)
        const float4* D4 = (const float4*)D;
        float4 acc4 = make_float4(0.f, 0.f, 0.f, 0.f);
        int total4 = 4096 * 1024;
        for (int i = (cta - 5) * TPB + t; i < total4; i += 123 * TPB) {
            float4 d = D4[i];
            acc4.x += d.x; acc4.y += d.y; acc4.z += d.z; acc4.w += d.w;
        }
        g_y[cta] = acc4.x + acc4.y + acc4.z + acc4.w;
    }
    gbar();   // 1

    float lam1 = *lam1p, lam2 = *lam2p, rho = *rhop;

    if (cta < 64) {
        for (int i = t; i < 4096; i += TPB) { int a = i >> 6, c = i & 63; sm.s.Ms[a*65 + c] = g_StS[i]; }
        __syncthreads();
    }

    // ---------------- apply: x_h = B_h^{-1} r_h (Jacobi, 64 threads/CTA) -------
    auto apply = [&](int useY, int nin) {
        if (cta < 64 && t < 64) {
            int h = cta, u = t;
            float r = g_b[h*64 + u];
            if (useY) r -= lam1 * g_y[h*64 + u];
            float Muu  = sm.s.Ms[u*65 + u];
            float dinv = 1.0f / (rho + g_qf[h*64 + u] + lam2 * Muu);
            float z = useY ? g_x[h*64 + u] : r * dinv;
            int cur = 0;
            sm.s.zs[0][u] = z;
            asm volatile("bar.sync 1, 64;" ::: "memory");
            for (int it = 0; it < nin; it++) {
                float a0=0.f,a1=0.f,a2=0.f,a3=0.f;
                const float* Mr = &sm.s.Ms[u*65];
                const float* zc = sm.s.zs[cur];
                #pragma unroll 16
                for (int c = 0; c < 64; c += 4) {
                    a0 += Mr[c]   * zc[c];
                    a1 += Mr[c+1] * zc[c+1];
                    a2 += Mr[c+2] * zc[c+2];
                    a3 += Mr[c+3] * zc[c+3];
                }
                float acc = (a0+a1) + (a2+a3);
                z = (r - lam2 * (acc - Muu * z)) * dinv;
                if (it + 1 < nin) {
                    sm.s.zs[cur^1][u] = z;
                    asm volatile("bar.sync 1, 64;" ::: "memory");
                    cur ^= 1;
                }
            }
            g_x[h*64 + u] = z;
        }
    };

    // ---------------- matvec: y = D x (all 128 CTAs) ---------------------------
    auto matvec = [&]() {
        const float4* x4 = (const float4*)g_x;
        float4* xs4 = (float4*)sm.s.xs;
        for (int i = t; i < 1024; i += TPB) xs4[i] = x4[i];
        __syncthreads();
        int w = t >> 5, lane = t & 31;
        int row0 = cta * 32 + w * 2;
        #pragma unroll
        for (int rr = 0; rr < 2; rr++) {
            int row = row0 + rr;
            const float4* D4 = (const float4*)(D + (size_t)row * 4096);
            float acc = 0.0f;
            #pragma unroll
            for (int it = 0; it < 32; it++) {
                float4 d  = D4[lane + 32*it];
                float4 xv = xs4[lane + 32*it];
                acc += d.x*xv.x + d.y*xv.y + d.z*xv.z + d.w*xv.w;
            }
            #pragma unroll
            for (int off = 16; off > 0; off >>= 1)
                acc += __shfl_xor_sync(0xffffffffu, acc, off);
            if (lane == 0) g_y[row] = acc;
        }
        __syncthreads();
    };

    apply(0, NIN0);
    gbar();   // 2
    for (int it = 0; it < FPITERS; it++) {
        matvec();
        gbar();
        apply(1, NIN1);
        gbar();
    }

    if (cta != 0) return;

    // ================= final: one-sided Jacobi SVD + SVT (CTA0 only) ==========
    float* Gf = sm.f.Gf;
    float4* Gc = (float4*)sm.f.Gf;      // column j: Gc[j*17 + i] = rows 4i..4i+3
    float* Xs = sm.f.Xs;
    float* nrm = sm.f.nrm;
    int lane = t & 31, w = t >> 5;

    for (int i = t; i < 4096; i += TPB) {
        int r = i >> 6, j = i & 63;
        float xv = g_x[i] + thP[i];
        Gf[j*68 + r] = xv;
        Xs[j*65 + r] = xv;
    }
    __syncthreads();
    if (t < 64) {
        float acc = 0.0f;
        #pragma unroll 16
        for (int r = 0; r < 64; r++) { float g = Gf[t*68 + r]; acc += g*g; }
        nrm[t] = acc;
    }
    __syncthreads();

    // Jacobi sweeps: 16 warps x 2 pairs (16-lane groups); lane kk owns float4 kk.
    {
        int grp = lane >> 4;
        int kk  = lane & 15;
        int k   = (w << 1) | grp;            // pair id 0..31
        for (int sweep = 0; sweep < MAXSWEEP; sweep++) {
            int p, q;
            if (k == 0) { p = 63; q = 0; }
            else { p = k; q = 63 - k; }
            for (int r = 0; r < 63; r++) {
                float4 gp = Gc[p*17 + kk];
                float4 gq = Gc[q*17 + kk];
                float dp = gp.x*gq.x + gp.y*gq.y + gp.z*gq.z + gp.w*gq.w;
                #pragma unroll
                for (int o = 8; o; o >>= 1) dp += __shfl_xor_sync(0xffffffffu, dp, o);
                float npp = nrm[p], nqq = nrm[q];
                if (dp*dp > JTHR * npp * nqq) {
                    float zeta = __fdividef(nqq - npp, 2.0f * dp);
                    float tt = copysignf(__fdividef(1.0f, fabsf(zeta) + __fsqrt_rn(1.0f + zeta*zeta)), zeta);
                    float c = __frsqrt_rn(1.0f + tt*tt), s = tt * c;
                    float4 a, b;
                    a.x = c*gp.x - s*gq.x;  b.x = s*gp.x + c*gq.x;
                    a.y = c*gp.y - s*gq.y;  b.y = s*gp.y + c*gq.y;
                    a.z = c*gp.z - s*gq.z;  b.z = s*gp.z + c*gq.z;
                    a.w = c*gp.w - s*gq.w;  b.w = s*gp.w + c*gq.w;
                    Gc[p*17 + kk] = a;
                    Gc[q*17 + kk] = b;
                    if (kk == 0) { nrm[p] = npp - tt*dp; nrm[q] = nqq + tt*dp; }
                }
                __syncthreads();
                if (k == 0) { q = (q + 1 == 63) ? 0 : q + 1; }
                else { p = (p + 1 == 63) ? 0 : p + 1; q = (q + 1 == 63) ? 0 : q + 1; }
            }
        }
    }

    // singular values + threshold + spectral factors w(n_i)
    if (t < 64) {
        float acc = 0.0f;
        #pragma unroll 16
        for (int r = 0; r < 64; r++) { float g = Gf[t*68 + r]; acc += g*g; }
        sm.f.sarr[t] = sqrtf(acc);
    }
    __syncthreads();
    if (t == 0) {
        float m = 0.0f;
        for (int j = 0; j < 64; j++) m = fmaxf(m, sm.f.sarr[j]);
        float vv = *vp;
        float tau = 0.4f / (1.0f + expf(-vv));
        sm.f.thr_s = tau * m;
    }
    __syncthreads();
    if (t < 64) {
        float s = sm.f.sarr[t];
        float st = s - sm.f.thr_s;
        sm.f.fsc[t] = (st > 0.0f) ? st / (s*s*s) : 0.0f;
    }
    __syncthreads();

    // ============ exact SVT identity: Ltmp = G * w(N) * G^T X, N = G^T G ======
    // w(N) approximated to FIRST order (Daleckii-Krein): M = diag(w_i) +
    // N_ij (w_j - w_i)/(n_j - n_i). Removes the O(offdiag) error of the
    // diagonal-only formula, so 5 sweeps suffice.
    int cc = t & 63;        // column index (lanes)
    int gg = t >> 6;        // row-block 8gg..8gg+7
    int ln = t & 31;
    float Nreg[8], Yreg[8];
    #pragma unroll
    for (int kk = 0; kk < 8; kk++) { Nreg[kk] = 0.f; Yreg[kk] = 0.f; }

    // Y[i][cc] = sum_r G[r][i] * X[r][cc]  (float4-broadcast G, scalar X)
    for (int rb = 0; rb < 16; rb++) {
        float xv0 = Xs[cc*65 + rb*4 + 0];
        float xv1 = Xs[cc*65 + rb*4 + 1];
        float xv2 = Xs[cc*65 + rb*4 + 2];
        float xv3 = Xs[cc*65 + rb*4 + 3];
        #pragma unroll
        for (int kk = 0; kk < 8; kk++) {
            float4 g4 = Gc[(8*gg + kk)*17 + rb];
            Yreg[kk] += g4.x*xv0 + g4.y*xv1 + g4.z*xv2 + g4.w*xv3;
        }
    }
    // N[i][cc] = sum_r G[r][i] * G[r][cc]  (lane-skewed r-order: conflict-free)
    for (int rr = 0; rr < 64; rr++) {
        int r = (rr + ln) & 63;
        float gj = Gf[cc*68 + r];
        #pragma unroll
        for (int kk = 0; kk < 8; kk++)
            Nreg[kk] += Gf[(8*gg + kk)*68 + r] * gj;
    }
    __syncthreads();
    // M -> g_b (gmem staging; g_b is dead after solve), Y -> Xs (X is dead)
    {
        float sj = sm.f.sarr[cc];
        float nj = sj*sj;
        float vj = sm.f.fsc[cc];
        #pragma unroll
        for (int kk = 0; kk < 8; kk++) {
            int i = 8*gg + kk;
            float si = sm.f.sarr[i];
            float ni = si*si;
            float vi = sm.f.fsc[i];
            float Mv;
            if (i == cc) Mv = vi;
            else {
                float dn = nj - ni;
                Mv = (fabsf(dn) > 1e-6f*(ni + nj) + 1e-30f)
                     ? Nreg[kk] * (vj - vi) / dn : 0.0f;
            }
            g_b[i*64 + cc] = Mv;
            Xs[i*65 + cc]  = Yreg[kk];
        }
    }
    __syncthreads();

    // Z = M * Y  (M broadcast from gmem/L1, Y from smem)
    float Zreg[8];
    #pragma unroll
    for (int kk = 0; kk < 8; kk++) Zreg[kk] = 0.f;
    for (int m = 0; m < 64; m++) {
        float ym = Xs[m*65 + cc];
        #pragma unroll
        for (int kk = 0; kk < 8; kk++)
            Zreg[kk] += g_b[(8*gg + kk)*64 + m] * ym;
    }
    __syncthreads();
    #pragma unroll
    for (int kk = 0; kk < 8; kk++) Xs[(8*gg + kk)*65 + cc] = Zreg[kk];
    __syncthreads();

    // Ltmp = G * Z ; Ptmp = thP + neta*(x - Ltmp)
    float neta = *netap;
    float Lreg[8];
    #pragma unroll
    for (int kk = 0; kk < 8; kk++) Lreg[kk] = 0.f;
    for (int j = 0; j < 64; j++) {
        float zv = Xs[j*65 + cc];
        float4 ga = Gc[j*17 + 2*gg];
        float4 gb = Gc[j*17 + 2*gg + 1];
        Lreg[0] += ga.x*zv; Lreg[1] += ga.y*zv; Lreg[2] += ga.z*zv; Lreg[3] += ga.w*zv;
        Lreg[4] += gb.x*zv; Lreg[5] += gb.y*zv; Lreg[6] += gb.z*zv; Lreg[7] += gb.w*zv;
    }
    #pragma unroll
    for (int kk = 0; kk < 8; kk++) {
        int idx = (8*gg + kk)*64 + cc;
        out[idx]        = Lreg[kk];
        out[4096 + idx] = thP[idx] + neta * (g_x[idx] - Lreg[kk]);
    }
}

// ---------------- launch ----------------
extern "C" void kernel_launch(void* const* d_in, const int* in_sizes, int n_in,
                              void* d_out, int out_size) {
    const float* inp  = (const float*)d_in[0];
    const float* L    = (const float*)d_in[1];
    const void*  mask = d_in[2];
    const float* D    = (const float*)d_in[3];
    const float* thP  = (const float*)d_in[4];
    const float* v    = (const float*)d_in[5];
    const float* neta = (const float*)d_in[6];
    const float* lam1 = (const float*)d_in[7];
    const float* lam2 = (const float*)d_in[8];
    const float* rho  = (const float*)d_in[9];
    const float* S    = (const float*)d_in[10];
    float* out = (float*)d_out;

    k_all<<<NCTA, TPB>>>(inp, L, mask, D, thP, v, neta, lam1, lam2, rho, S, out);
}

// round 12
// speedup vs baseline: 1.4097x; 1.4097x over previous
#include <cuda_runtime.h>
#include <cuda_bf16.h>

#define NCTA 128
#define TPB  512
#define FPITERS 2
#define NIN0 12
#define NIN1 8
#define MAXSWEEP 5
#define JTHR 1e-13f

// ---------------- device scratch (no allocation allowed) ----------------
__device__ __align__(16) float g_qf[4096];
__device__ __align__(16) float g_StS[4096];
__device__ __align__(16) float g_b[4096];
__device__ __align__(16) float g_x[4096];
__device__ __align__(16) float g_y[4096];
__device__ int g_cnt = 0;
__device__ int g_gen = 0;   // monotone across graph replays; g_cnt self-resets

// device-wide barrier: replay-safe (cnt self-resets; gen only increments)
__device__ __forceinline__ void gbar() {
    __threadfence();
    __syncthreads();
    if (threadIdx.x == 0) {
        int my = *(volatile int*)&g_gen;
        int old = atomicAdd(&g_cnt, 1);
        if (old == NCTA - 1) {
            g_cnt = 0;
            __threadfence();
            atomicAdd(&g_gen, 1);
        } else {
            while (*(volatile int*)&g_gen == my) { }
        }
    }
    __syncthreads();
    __threadfence();
}

struct SolveSm {
    float Ms[64*65];      // StS (apply); Ss staging (prep)
    float xs[4096];       // matvec x cache
    float zs[2][64];      // apply double buffer
};
struct FinalSm {
    float Gf[64*68];      // column j at Gf[j*68 + r]; 17 float4s per column
    float Xs[64*65];      // pristine X; then Y = G^T X; then Z = M Y
    float nrm[64];
    float sarr[64];
    float fsc[64];
    float thr_s;
};
union __align__(16) Smem { SolveSm s; FinalSm f; };

__global__ void __launch_bounds__(TPB, 1)
k_all(const float* __restrict__ inp, const float* __restrict__ L,
      const void* __restrict__ mask, const float* __restrict__ D,
      const float* __restrict__ thP, const float* __restrict__ vp,
      const float* __restrict__ netap, const float* __restrict__ lam1p,
      const float* __restrict__ lam2p, const float* __restrict__ rhop,
      const float* __restrict__ S, float* __restrict__ out) {
    __shared__ Smem sm;
    __shared__ int s_badU8, s_off1;
    int t = threadIdx.x;
    int cta = blockIdx.x;

    // ================= phase 0: prep (CTA0), StS (CTA1-4), D L2-warm (rest) ====
    if (cta == 0) {
        if (t == 0) { s_badU8 = 0; s_off1 = 0; }
        __syncthreads();
        const unsigned char* m8 = (const unsigned char*)mask;
        int b1 = 0, b2 = 0;
        for (int i = t; i < 4096; i += TPB) {
            unsigned v = m8[i];
            if (v > 1u) b1 = 1;
            if (v == 1u && (i & 3) != 0) b2 = 1;
        }
        if (b1) s_badU8 = 1;        // benign races
        if (b2) s_off1 = 1;
        __syncthreads();
        int mode = s_badU8 ? 1 : (s_off1 ? 0 : 2);   // 0=u8,1=f32,2=i32
        float rho = *rhop;
        for (int i = t; i < 4096; i += TPB) {
            bool on;
            if (mode == 0)      on = ((const unsigned char*)mask)[i] != 0;
            else if (mode == 1) on = ((const float*)mask)[i] != 0.0f;
            else                on = ((const int*)mask)[i] != 0;
            g_qf[i] = on ? 1.0f : 0.0f;
            g_b[i]  = rho * (L[i] - thP[i]) + (on ? inp[i] : 0.0f);
        }
    } else if (cta <= 4) {
        for (int i = t; i < 4096; i += TPB) { int h = i >> 6, a = i & 63; sm.s.Ms[h*65 + a] = S[i]; }
        __syncthreads();
        int base = (cta - 1) * 1024;
        #pragma unroll
        for (int k = 0; k < 2; k++) {
            int idx = base + t + k*TPB;
            int a = idx >> 6, b = idx & 63;
            float acc = 0.0f;
            #pragma unroll 16
            for (int h = 0; h < 64; h++) acc += sm.s.Ms[h*65 + a] * sm.s.Ms[h*65 + b];
            g_StS[idx] = acc;
        }
    } else {
        // warm D into L2 (sink into g_y; fully overwritten by first matvec)
        const float4* D4 = (const float4*)D;
        float4 acc4 = make_float4(0.f, 0.f, 0.f, 0.f);
        int total4 = 4096 * 1024;
        for (int i = (cta - 5) * TPB + t; i < total4; i += 123 * TPB) {
            float4 d = D4[i];
            acc4.x += d.x; acc4.y += d.y; acc4.z += d.z; acc4.w += d.w;
        }
        g_y[cta] = acc4.x + acc4.y + acc4.z + acc4.w;
    }
    gbar();   // 1

    float lam1 = *lam1p, lam2 = *lam2p, rho = *rhop;

    if (cta < 64) {
        for (int i = t; i < 4096; i += TPB) { int a = i >> 6, c = i & 63; sm.s.Ms[a*65 + c] = g_StS[i]; }
        __syncthreads();
    }

    // ---------------- apply: x_h = B_h^{-1} r_h (Jacobi, 64 threads/CTA) -------
    auto apply = [&](int useY, int nin) {
        if (cta < 64 && t < 64) {
            int h = cta, u = t;
            float r = g_b[h*64 + u];
            if (useY) r -= lam1 * g_y[h*64 + u];
            float Muu  = sm.s.Ms[u*65 + u];
            float dinv = 1.0f / (rho + g_qf[h*64 + u] + lam2 * Muu);
            float z = useY ? g_x[h*64 + u] : r * dinv;
            int cur = 0;
            sm.s.zs[0][u] = z;
            asm volatile("bar.sync 1, 64;" ::: "memory");
            for (int it = 0; it < nin; it++) {
                float a0=0.f,a1=0.f,a2=0.f,a3=0.f;
                const float* Mr = &sm.s.Ms[u*65];
                const float* zc = sm.s.zs[cur];
                #pragma unroll 16
                for (int c = 0; c < 64; c += 4) {
                    a0 += Mr[c]   * zc[c];
                    a1 += Mr[c+1] * zc[c+1];
                    a2 += Mr[c+2] * zc[c+2];
                    a3 += Mr[c+3] * zc[c+3];
                }
                float acc = (a0+a1) + (a2+a3);
                z = (r - lam2 * (acc - Muu * z)) * dinv;
                if (it + 1 < nin) {
                    sm.s.zs[cur^1][u] = z;
                    asm volatile("bar.sync 1, 64;" ::: "memory");
                    cur ^= 1;
                }
            }
            g_x[h*64 + u] = z;
        }
    };

    // ---------------- matvec: y = D x (all 128 CTAs) ---------------------------
    auto matvec = [&]() {
        const float4* x4 = (const float4*)g_x;
        float4* xs4 = (float4*)sm.s.xs;
        for (int i = t; i < 1024; i += TPB) xs4[i] = x4[i];
        __syncthreads();
        int w = t >> 5, lane = t & 31;
        int row0 = cta * 32 + w * 2;
        #pragma unroll
        for (int rr = 0; rr < 2; rr++) {
            int row = row0 + rr;
            const float4* D4 = (const float4*)(D + (size_t)row * 4096);
            float acc = 0.0f;
            #pragma unroll
            for (int it = 0; it < 32; it++) {
                float4 d  = D4[lane + 32*it];
                float4 xv = xs4[lane + 32*it];
                acc += d.x*xv.x + d.y*xv.y + d.z*xv.z + d.w*xv.w;
            }
            #pragma unroll
            for (int off = 16; off > 0; off >>= 1)
                acc += __shfl_xor_sync(0xffffffffu, acc, off);
            if (lane == 0) g_y[row] = acc;
        }
        __syncthreads();
    };

    apply(0, NIN0);
    gbar();   // 2
    for (int it = 0; it < FPITERS; it++) {
        matvec();
        gbar();
        apply(1, NIN1);
        gbar();
    }

    if (cta != 0) return;

    // ================= final: one-sided Jacobi SVD + SVT (CTA0 only) ==========
    float* Gf = sm.f.Gf;
    float4* Gc = (float4*)sm.f.Gf;      // column j: Gc[j*17 + i] = rows 4i..4i+3
    float* Xs = sm.f.Xs;
    float* nrm = sm.f.nrm;
    int lane = t & 31, w = t >> 5;

    for (int i = t; i < 4096; i += TPB) {
        int r = i >> 6, j = i & 63;
        float xv = g_x[i] + thP[i];
        Gf[j*68 + r] = xv;
        Xs[j*65 + r] = xv;
    }
    __syncthreads();
    if (t < 64) {
        float acc = 0.0f;
        #pragma unroll 16
        for (int r = 0; r < 64; r++) { float g = Gf[t*68 + r]; acc += g*g; }
        nrm[t] = acc;
    }
    __syncthreads();

    // Jacobi: 16 warps x 2 pairs (16-lane groups); lane kk owns float4 block kk.
    {
        int grp = lane >> 4;
        int kk  = lane & 15;
        int k   = (w << 1) | grp;            // pair id 0..31
        for (int sweep = 0; sweep < MAXSWEEP; sweep++) {
            int p, q;
            if (k == 0) { p = 63; q = 0; }
            else { p = k; q = 63 - k; }
            for (int r = 0; r < 63; r++) {
                float4 gp = Gc[p*17 + kk];
                float4 gq = Gc[q*17 + kk];
                float dp = gp.x*gq.x + gp.y*gq.y + gp.z*gq.z + gp.w*gq.w;
                #pragma unroll
                for (int o = 8; o; o >>= 1) dp += __shfl_xor_sync(0xffffffffu, dp, o);
                float npp = nrm[p], nqq = nrm[q];
                if (dp*dp > JTHR * npp * nqq) {
                    float zeta = __fdividef(nqq - npp, 2.0f * dp);
                    float tt = copysignf(__fdividef(1.0f, fabsf(zeta) + __fsqrt_rn(1.0f + zeta*zeta)), zeta);
                    float c = __frsqrt_rn(1.0f + tt*tt), s = tt * c;
                    float4 a, b;
                    a.x = c*gp.x - s*gq.x;  b.x = s*gp.x + c*gq.x;
                    a.y = c*gp.y - s*gq.y;  b.y = s*gp.y + c*gq.y;
                    a.z = c*gp.z - s*gq.z;  b.z = s*gp.z + c*gq.z;
                    a.w = c*gp.w - s*gq.w;  b.w = s*gp.w + c*gq.w;
                    Gc[p*17 + kk] = a;
                    Gc[q*17 + kk] = b;
                    if (kk == 0) { nrm[p] = npp - tt*dp; nrm[q] = nqq + tt*dp; }
                }
                __syncthreads();
                if (k == 0) { q = (q + 1 == 63) ? 0 : q + 1; }
                else { p = (p + 1 == 63) ? 0 : p + 1; q = (q + 1 == 63) ? 0 : q + 1; }
            }
        }
    }

    // singular values + threshold + spectral factors w(n_i)
    if (t < 64) {
        float acc = 0.0f;
        #pragma unroll 16
        for (int r = 0; r < 64; r++) { float g = Gf[t*68 + r]; acc += g*g; }
        sm.f.sarr[t] = sqrtf(acc);
    }
    __syncthreads();
    if (t == 0) {
        float m = 0.0f;
        for (int j = 0; j < 64; j++) m = fmaxf(m, sm.f.sarr[j]);
        float vv = *vp;
        float tau = 0.4f / (1.0f + expf(-vv));
        sm.f.thr_s = tau * m;
    }
    __syncthreads();
    if (t < 64) {
        float s = sm.f.sarr[t];
        float st = s - sm.f.thr_s;
        sm.f.fsc[t] = (st > 0.0f) ? st / (s*s*s) : 0.0f;
    }
    __syncthreads();

    // ======= SVT with first-order Daleckii-Krein correction (R9 loop style) ====
    // Ltmp = G M G^T X with M = diag(w_i) + N_ij (w_j - w_i)/(n_j - n_i),
    // N = G^T G. M staged in out[0..4095] (dead scratch until final write).

    // Phase A: Y[jj][c] = sum_r G[r,jj] X[r,c]   (into registers)
    float yreg[8];
    #pragma unroll
    for (int kq = 0; kq < 8; kq++) {
        int idx = t + kq*TPB;
        int jj = idx >> 6, c = idx & 63;
        float acc = 0.0f;
        #pragma unroll 16
        for (int r = 0; r < 64; r++) acc += Gf[jj*68 + r] * Xs[c*65 + r];
        yreg[kq] = acc;
    }
    // Phase B: N[jj][c] (lane-skewed, conflict-free) -> M -> out[jj*64 + c]
    #pragma unroll
    for (int kq = 0; kq < 8; kq++) {
        int idx = t + kq*TPB;
        int jj = idx >> 6, c = idx & 63;
        float acc = 0.0f;
        for (int rr = 0; rr < 64; rr++) {
            int r = (rr + lane) & 63;
            acc += Gf[jj*68 + r] * Gf[c*68 + r];
        }
        float Mv;
        if (jj == c) Mv = sm.f.fsc[jj];
        else {
            float si = sm.f.sarr[jj], sj = sm.f.sarr[c];
            float ni = si*si, nj = sj*sj;
            float dn = nj - ni;
            Mv = (fabsf(dn) > 1e-6f*(ni + nj) + 1e-30f)
                 ? acc * (sm.f.fsc[c] - sm.f.fsc[jj]) / dn : 0.0f;
        }
        out[jj*64 + c] = Mv;
    }
    __syncthreads();            // all X reads done
    #pragma unroll
    for (int kq = 0; kq < 8; kq++) {
        int idx = t + kq*TPB;
        int jj = idx >> 6, c = idx & 63;
        Xs[c*65 + jj] = yreg[kq];   // Y, transposed layout
    }
    __syncthreads();

    // Phase C: Z[jj][c] = sum_m M[jj][m] Y[m][c]  (M broadcast LDG, Y smem)
    #pragma unroll
    for (int kq = 0; kq < 8; kq++) {
        int idx = t + kq*TPB;
        int jj = idx >> 6, c = idx & 63;
        float acc = 0.0f;
        #pragma unroll 16
        for (int m = 0; m < 64; m++) acc += out[jj*64 + m] * Xs[c*65 + m];
        yreg[kq] = acc;
    }
    __syncthreads();            // all Y reads done
    #pragma unroll
    for (int kq = 0; kq < 8; kq++) {
        int idx = t + kq*TPB;
        int jj = idx >> 6, c = idx & 63;
        Xs[c*65 + jj] = yreg[kq];   // Z, transposed layout
    }
    __syncthreads();

    // Phase D: Ltmp = G Z ; Ptmp = thP + neta*(x - Ltmp)
    float neta = *netap;
    #pragma unroll
    for (int kq = 0; kq < 8; kq++) {
        int i = t + kq*TPB;
        int r = i >> 6, c = i & 63;
        float acc = 0.0f;
        #pragma unroll 16
        for (int j = 0; j < 64; j++) acc += Gf[j*68 + r] * Xs[c*65 + j];
        out[i]        = acc;
        out[4096 + i] = thP[i] + neta * (g_x[i] - acc);
    }
}

// ---------------- launch ----------------
extern "C" void kernel_launch(void* const* d_in, const int* in_sizes, int n_in,
                              void* d_out, int out_size) {
    const float* inp  = (const float*)d_in[0];
    const float* L    = (const float*)d_in[1];
    const void*  mask = d_in[2];
    const float* D    = (const float*)d_in[3];
    const float* thP  = (const float*)d_in[4];
    const float* v    = (const float*)d_in[5];
    const float* neta = (const float*)d_in[6];
    const float* lam1 = (const float*)d_in[7];
    const float* lam2 = (const float*)d_in[8];
    const float* rho  = (const float*)d_in[9];
    const float* S    = (const float*)d_in[10];
    float* out = (float*)d_out;

    k_all<<<NCTA, TPB>>>(inp, L, mask, D, thP, v, neta, lam1, lam2, rho, S, out);
}

// round 13
// speedup vs baseline: 1.6973x; 1.2040x over previous
#include <cuda_runtime.h>
#include <cuda_bf16.h>

#define NCTA 128
#define TPB  512
#define FPITERS 1
#define NIN0 12
#define NIN1 10
#define MAXSWEEP 5
#define JTHR 1e-13f

// ---------------- device scratch (no allocation allowed) ----------------
__device__ __align__(16) float g_qf[4096];   // mask; later Z
__device__ __align__(16) float g_StS[4096];  // StS; later G (row-major)
__device__ __align__(16) float g_b[4096];    // rhs; later M
__device__ __align__(16) float g_x[4096];
__device__ __align__(16) float g_y[4096];    // matvec y; later Y
__device__ float g_sv[64];
__device__ float g_fs[64];
__device__ int g_cnt = 0;
__device__ int g_gen = 0;   // monotone across graph replays; g_cnt self-resets

// device-wide barrier: replay-safe (cnt self-resets; gen only increments)
__device__ __forceinline__ void gbar() {
    __threadfence();
    __syncthreads();
    if (threadIdx.x == 0) {
        int my = *(volatile int*)&g_gen;
        int old = atomicAdd(&g_cnt, 1);
        if (old == NCTA - 1) {
            g_cnt = 0;
            __threadfence();
            atomicAdd(&g_gen, 1);
        } else {
            while (*(volatile int*)&g_gen == my) { }
        }
    }
    __syncthreads();
    __threadfence();
}

struct SolveSm {
    float Ms[64*65];      // StS (apply); Ss staging (prep)
    float xs[4096];       // matvec x cache
    float zs[2][64];      // apply double buffer
};
struct FinalSm {
    float Gf[64*68];      // column j at Gf[j*68 + r]; 17 float4s per column
    float nrm[64];
    float sarr[64];
    float fsc[64];
    float thr_s;
};
union __align__(16) Smem { SolveSm s; FinalSm f; };

__global__ void __launch_bounds__(TPB, 1)
k_all(const float* __restrict__ inp, const float* __restrict__ L,
      const void* __restrict__ mask, const float* __restrict__ D,
      const float* __restrict__ thP, const float* __restrict__ vp,
      const float* __restrict__ netap, const float* __restrict__ lam1p,
      const float* __restrict__ lam2p, const float* __restrict__ rhop,
      const float* __restrict__ S, float* __restrict__ out) {
    __shared__ Smem sm;
    __shared__ int s_badU8, s_off1;
    int t = threadIdx.x;
    int cta = blockIdx.x;

    // ================= phase 0: prep (CTA0), StS (CTA1-4), D L2-warm (rest) ====
    if (cta == 0) {
        if (t == 0) { s_badU8 = 0; s_off1 = 0; }
        __syncthreads();
        const unsigned char* m8 = (const unsigned char*)mask;
        int b1 = 0, b2 = 0;
        for (int i = t; i < 4096; i += TPB) {
            unsigned v = m8[i];
            if (v > 1u) b1 = 1;
            if (v == 1u && (i & 3) != 0) b2 = 1;
        }
        if (b1) s_badU8 = 1;        // benign races
        if (b2) s_off1 = 1;
        __syncthreads();
        int mode = s_badU8 ? 1 : (s_off1 ? 0 : 2);   // 0=u8,1=f32,2=i32
        float rho = *rhop;
        for (int i = t; i < 4096; i += TPB) {
            bool on;
            if (mode == 0)      on = ((const unsigned char*)mask)[i] != 0;
            else if (mode == 1) on = ((const float*)mask)[i] != 0.0f;
            else                on = ((const int*)mask)[i] != 0;
            g_qf[i] = on ? 1.0f : 0.0f;
            g_b[i]  = rho * (L[i] - thP[i]) + (on ? inp[i] : 0.0f);
        }
    } else if (cta <= 4) {
        for (int i = t; i < 4096; i += TPB) { int h = i >> 6, a = i & 63; sm.s.Ms[h*65 + a] = S[i]; }
        __syncthreads();
        int base = (cta - 1) * 1024;
        #pragma unroll
        for (int k = 0; k < 2; k++) {
            int idx = base + t + k*TPB;
            int a = idx >> 6, b = idx & 63;
            float acc = 0.0f;
            #pragma unroll 16
            for (int h = 0; h < 64; h++) acc += sm.s.Ms[h*65 + a] * sm.s.Ms[h*65 + b];
            g_StS[idx] = acc;
        }
    } else {
        // warm D into L2 (sink into g_y; fully overwritten by first matvec)
        const float4* D4 = (const float4*)D;
        float4 acc4 = make_float4(0.f, 0.f, 0.f, 0.f);
        int total4 = 4096 * 1024;
        for (int i = (cta - 5) * TPB + t; i < total4; i += 123 * TPB) {
            float4 d = D4[i];
            acc4.x += d.x; acc4.y += d.y; acc4.z += d.z; acc4.w += d.w;
        }
        g_y[cta] = acc4.x + acc4.y + acc4.z + acc4.w;
    }
    gbar();   // 1

    float lam1 = *lam1p, lam2 = *lam2p, rho = *rhop;

    if (cta < 64) {
        for (int i = t; i < 4096; i += TPB) { int a = i >> 6, c = i & 63; sm.s.Ms[a*65 + c] = g_StS[i]; }
        __syncthreads();
    }

    // ---------------- apply: x_h = B_h^{-1} r_h (Jacobi, 64 threads/CTA) -------
    auto apply = [&](int useY, int nin) {
        if (cta < 64 && t < 64) {
            int h = cta, u = t;
            float r = g_b[h*64 + u];
            if (useY) r -= lam1 * g_y[h*64 + u];
            float Muu  = sm.s.Ms[u*65 + u];
            float dinv = 1.0f / (rho + g_qf[h*64 + u] + lam2 * Muu);
            float z = useY ? g_x[h*64 + u] : r * dinv;
            int cur = 0;
            sm.s.zs[0][u] = z;
            asm volatile("bar.sync 1, 64;" ::: "memory");
            for (int it = 0; it < nin; it++) {
                float a0=0.f,a1=0.f,a2=0.f,a3=0.f;
                const float* Mr = &sm.s.Ms[u*65];
                const float* zc = sm.s.zs[cur];
                #pragma unroll 16
                for (int c = 0; c < 64; c += 4) {
                    a0 += Mr[c]   * zc[c];
                    a1 += Mr[c+1] * zc[c+1];
                    a2 += Mr[c+2] * zc[c+2];
                    a3 += Mr[c+3] * zc[c+3];
                }
                float acc = (a0+a1) + (a2+a3);
                z = (r - lam2 * (acc - Muu * z)) * dinv;
                if (it + 1 < nin) {
                    sm.s.zs[cur^1][u] = z;
                    asm volatile("bar.sync 1, 64;" ::: "memory");
                    cur ^= 1;
                }
            }
            g_x[h*64 + u] = z;
        }
    };

    // ---------------- matvec: y = D x (all 128 CTAs) ---------------------------
    auto matvec = [&]() {
        const float4* x4 = (const float4*)g_x;
        float4* xs4 = (float4*)sm.s.xs;
        for (int i = t; i < 1024; i += TPB) xs4[i] = x4[i];
        __syncthreads();
        int w = t >> 5, lane = t & 31;
        int row0 = cta * 32 + w * 2;
        #pragma unroll
        for (int rr = 0; rr < 2; rr++) {
            int row = row0 + rr;
            const float4* D4 = (const float4*)(D + (size_t)row * 4096);
            float acc = 0.0f;
            #pragma unroll
            for (int it = 0; it < 32; it++) {
                float4 d  = D4[lane + 32*it];
                float4 xv = xs4[lane + 32*it];
                acc += d.x*xv.x + d.y*xv.y + d.z*xv.z + d.w*xv.w;
            }
            #pragma unroll
            for (int off = 16; off > 0; off >>= 1)
                acc += __shfl_xor_sync(0xffffffffu, acc, off);
            if (lane == 0) g_y[row] = acc;
        }
        __syncthreads();
    };

    apply(0, NIN0);
    gbar();   // 2
    for (int it = 0; it < FPITERS; it++) {
        matvec();
        gbar();
        apply(1, NIN1);
        gbar();
    }

    // ================= Jacobi SVD on CTA0; others wait at next gbar ===========
    if (cta == 0) {
        float* Gf = sm.f.Gf;
        float4* Gc = (float4*)sm.f.Gf;
        float* nrm = sm.f.nrm;
        int lane = t & 31, w = t >> 5;

        for (int i = t; i < 4096; i += TPB) {
            int r = i >> 6, j = i & 63;
            Gf[j*68 + r] = g_x[i] + thP[i];
        }
        __syncthreads();
        if (t < 64) {
            float acc = 0.0f;
            #pragma unroll 16
            for (int r = 0; r < 64; r++) { float g = Gf[t*68 + r]; acc += g*g; }
            nrm[t] = acc;
        }
        __syncthreads();

        // 16 warps x 2 pairs (16-lane groups); lane kk owns float4 block kk.
        {
            int grp = lane >> 4;
            int kk  = lane & 15;
            int k   = (w << 1) | grp;            // pair id 0..31
            for (int sweep = 0; sweep < MAXSWEEP; sweep++) {
                int p, q;
                if (k == 0) { p = 63; q = 0; }
                else { p = k; q = 63 - k; }
                for (int r = 0; r < 63; r++) {
                    float4 gp = Gc[p*17 + kk];
                    float4 gq = Gc[q*17 + kk];
                    float dp = gp.x*gq.x + gp.y*gq.y + gp.z*gq.z + gp.w*gq.w;
                    #pragma unroll
                    for (int o = 8; o; o >>= 1) dp += __shfl_xor_sync(0xffffffffu, dp, o);
                    float npp = nrm[p], nqq = nrm[q];
                    if (dp*dp > JTHR * npp * nqq) {
                        float zeta = __fdividef(nqq - npp, 2.0f * dp);
                        float tt = copysignf(__fdividef(1.0f, fabsf(zeta) + __fsqrt_rn(1.0f + zeta*zeta)), zeta);
                        float c = __frsqrt_rn(1.0f + tt*tt), s = tt * c;
                        float4 a, b;
                        a.x = c*gp.x - s*gq.x;  b.x = s*gp.x + c*gq.x;
                        a.y = c*gp.y - s*gq.y;  b.y = s*gp.y + c*gq.y;
                        a.z = c*gp.z - s*gq.z;  b.z = s*gp.z + c*gq.z;
                        a.w = c*gp.w - s*gq.w;  b.w = s*gp.w + c*gq.w;
                        Gc[p*17 + kk] = a;
                        Gc[q*17 + kk] = b;
                        if (kk == 0) { nrm[p] = npp - tt*dp; nrm[q] = nqq + tt*dp; }
                    }
                    __syncthreads();
                    if (k == 0) { q = (q + 1 == 63) ? 0 : q + 1; }
                    else { p = (p + 1 == 63) ? 0 : p + 1; q = (q + 1 == 63) ? 0 : q + 1; }
                }
            }
        }

        // singular values + threshold + spectral factors
        if (t < 64) {
            float acc = 0.0f;
            #pragma unroll 16
            for (int r = 0; r < 64; r++) { float g = Gf[t*68 + r]; acc += g*g; }
            sm.f.sarr[t] = sqrtf(acc);
        }
        __syncthreads();
        if (t == 0) {
            float m = 0.0f;
            for (int j = 0; j < 64; j++) m = fmaxf(m, sm.f.sarr[j]);
            float vv = *vp;
            float tau = 0.4f / (1.0f + expf(-vv));
            sm.f.thr_s = tau * m;
        }
        __syncthreads();
        if (t < 64) {
            float s = sm.f.sarr[t];
            float st = s - sm.f.thr_s;
            g_sv[t] = s;
            g_fs[t] = (st > 0.0f) ? st / (s*s*s) : 0.0f;
        }
        // dump G row-major: gG[r*64 + j] = G[r][j]  (into dead g_StS)
        for (int i = t; i < 4096; i += TPB) {
            int r = i >> 6, j = i & 63;
            g_StS[i] = Gf[j*68 + r];
        }
    }
    gbar();   // Jacobi results visible

    // ======= parallel DK epilogue: Ltmp = G M G^T X, M = DK(w, N) =============
    float neta = *netap;

    // Phase A (ctas 0-7): Y[i][c] = sum_r G[r][i] X[r][c]; N -> M
    if (cta < 8) {
        int idx = cta * TPB + t;
        int i = idx >> 6, c = idx & 63;     // i uniform per warp -> broadcast
        float accY = 0.0f, accN = 0.0f;
        #pragma unroll 8
        for (int r = 0; r < 64; r++) {
            float gri = g_StS[r*64 + i];
            accY += gri * (g_x[r*64 + c] + thP[r*64 + c]);
            accN += gri * g_StS[r*64 + c];
        }
        g_y[idx] = accY;
        float Mv;
        if (i == c) Mv = g_fs[i];
        else {
            float si = g_sv[i], sj = g_sv[c];
            float ni = si*si, nj = sj*sj, dn = nj - ni;
            Mv = (fabsf(dn) > 1e-6f*(ni + nj) + 1e-30f)
                 ? accN * (g_fs[c] - g_fs[i]) / dn : 0.0f;
        }
        g_b[idx] = Mv;
    }
    gbar();

    // Phase B (ctas 0-7): Z[i][c] = sum_m M[i][m] Y[m][c]
    if (cta < 8) {
        int idx = cta * TPB + t;
        int i = idx >> 6, c = idx & 63;
        float acc = 0.0f;
        #pragma unroll 8
        for (int m = 0; m < 64; m++) acc += g_b[i*64 + m] * g_y[m*64 + c];
        g_qf[idx] = acc;
    }
    gbar();

    // Phase C (ctas 0-7): Ltmp = G Z ; Ptmp = thP + neta*(x - Ltmp)
    if (cta < 8) {
        int idx = cta * TPB + t;
        int r = idx >> 6, c = idx & 63;
        float acc = 0.0f;
        #pragma unroll 8
        for (int j = 0; j < 64; j++) acc += g_StS[r*64 + j] * g_qf[j*64 + c];
        out[idx]        = acc;
        out[4096 + idx] = thP[idx] + neta * (g_x[idx] - acc);
    }
}

// ---------------- launch ----------------
extern "C" void kernel_launch(void* const* d_in, const int* in_sizes, int n_in,
                              void* d_out, int out_size) {
    const float* inp  = (const float*)d_in[0];
    const float* L    = (const float*)d_in[1];
    const void*  mask = d_in[2];
    const float* D    = (const float*)d_in[3];
    const float* thP  = (const float*)d_in[4];
    const float* v    = (const float*)d_in[5];
    const float* neta = (const float*)d_in[6];
    const float* lam1 = (const float*)d_in[7];
    const float* lam2 = (const float*)d_in[8];
    const float* rho  = (const float*)d_in[9];
    const float* S    = (const float*)d_in[10];
    float* out = (float*)d_out;

    k_all<<<NCTA, TPB>>>(inp, L, mask, D, thP, v, neta, lam1, lam2, rho, S, out);
}

// round 14
// speedup vs baseline: 1.7371x; 1.0235x over previous
#include <cuda_runtime.h>
#include <cuda_bf16.h>

#define NCTA 128
#define TPB  512
#define FPITERS 1
#define NIN0 10
#define NIN1 8
#define MAXSWEEP 5

// ---------------- device scratch (no allocation allowed) ----------------
__device__ __align__(16) float g_qf[4096];   // mask; later Z
__device__ __align__(16) float g_StS[4096];  // StS; later G (row-major)
__device__ __align__(16) float g_b[4096];    // rhs; later M
__device__ __align__(16) float g_x[4096];
__device__ __align__(16) float g_y[4096];    // matvec y; later Y
__device__ float g_sv[64];
__device__ float g_fs[64];
__device__ int g_cnt = 0;
__device__ int g_gen = 0;    // 128-CTA barrier (monotone gen; replay-safe)
__device__ int g_cnt8 = 0;
__device__ int g_gen8 = 0;   // 8-CTA barrier for the epilogue

// device-wide barrier: replay-safe (cnt self-resets; gen only increments)
__device__ __forceinline__ void gbar_n(int n, int* cnt, int* gen) {
    __threadfence();
    __syncthreads();
    if (threadIdx.x == 0) {
        int my = *(volatile int*)gen;
        int old = atomicAdd(cnt, 1);
        if (old == n - 1) {
            *cnt = 0;
            __threadfence();
            atomicAdd(gen, 1);
        } else {
            while (*(volatile int*)gen == my) { }
        }
    }
    __syncthreads();
    __threadfence();
}
__device__ __forceinline__ void gbar()  { gbar_n(NCTA, &g_cnt,  &g_gen);  }
__device__ __forceinline__ void gbar8() { gbar_n(8,    &g_cnt8, &g_gen8); }

struct SolveSm {
    float Ms[64*65];      // StS (apply); Ss staging (prep)
    float xs[4096];       // matvec x cache
    float zs[2][64];      // apply double buffer
};
struct FinalSm {
    float Gf[64*68];      // column j at Gf[j*68 + r]; 17 float4s per column
    float nrm[64];
    float sarr[64];
    float thr_s;
};
union __align__(16) Smem { SolveSm s; FinalSm f; };

__global__ void __launch_bounds__(TPB, 1)
k_all(const float* __restrict__ inp, const float* __restrict__ L,
      const void* __restrict__ mask, const float* __restrict__ D,
      const float* __restrict__ thP, const float* __restrict__ vp,
      const float* __restrict__ netap, const float* __restrict__ lam1p,
      const float* __restrict__ lam2p, const float* __restrict__ rhop,
      const float* __restrict__ S, float* __restrict__ out) {
    __shared__ Smem sm;
    __shared__ int s_badU8, s_off1;
    int t = threadIdx.x;
    int cta = blockIdx.x;

    // ================= phase 0: prep (CTA0), StS (CTA1-4) =====================
    if (cta == 0) {
        if (t == 0) { s_badU8 = 0; s_off1 = 0; }
        __syncthreads();
        const unsigned char* m8 = (const unsigned char*)mask;
        int b1 = 0, b2 = 0;
        for (int i = t; i < 4096; i += TPB) {
            unsigned v = m8[i];
            if (v > 1u) b1 = 1;
            if (v == 1u && (i & 3) != 0) b2 = 1;
        }
        if (b1) s_badU8 = 1;        // benign races
        if (b2) s_off1 = 1;
        __syncthreads();
        int mode = s_badU8 ? 1 : (s_off1 ? 0 : 2);   // 0=u8,1=f32,2=i32
        float rho = *rhop;
        for (int i = t; i < 4096; i += TPB) {
            bool on;
            if (mode == 0)      on = ((const unsigned char*)mask)[i] != 0;
            else if (mode == 1) on = ((const float*)mask)[i] != 0.0f;
            else                on = ((const int*)mask)[i] != 0;
            g_qf[i] = on ? 1.0f : 0.0f;
            g_b[i]  = rho * (L[i] - thP[i]) + (on ? inp[i] : 0.0f);
        }
    } else if (cta <= 4) {
        for (int i = t; i < 4096; i += TPB) { int h = i >> 6, a = i & 63; sm.s.Ms[h*65 + a] = S[i]; }
        __syncthreads();
        int base = (cta - 1) * 1024;
        #pragma unroll
        for (int k = 0; k < 2; k++) {
            int idx = base + t + k*TPB;
            int a = idx >> 6, b = idx & 63;
            float acc = 0.0f;
            #pragma unroll 16
            for (int h = 0; h < 64; h++) acc += sm.s.Ms[h*65 + a] * sm.s.Ms[h*65 + b];
            g_StS[idx] = acc;
        }
    }
    gbar();   // 1

    float lam1 = *lam1p, lam2 = *lam2p, rho = *rhop;

    if (cta < 64) {
        for (int i = t; i < 4096; i += TPB) { int a = i >> 6, c = i & 63; sm.s.Ms[a*65 + c] = g_StS[i]; }
        __syncthreads();
    }

    // ---------------- apply: x_h = B_h^{-1} r_h (Jacobi, 64 threads/CTA) -------
    auto apply = [&](int useY, int nin) {
        if (cta < 64 && t < 64) {
            int h = cta, u = t;
            float r = g_b[h*64 + u];
            if (useY) r -= lam1 * g_y[h*64 + u];
            float Muu  = sm.s.Ms[u*65 + u];
            float dinv = 1.0f / (rho + g_qf[h*64 + u] + lam2 * Muu);
            float z = useY ? g_x[h*64 + u] : r * dinv;
            int cur = 0;
            sm.s.zs[0][u] = z;
            asm volatile("bar.sync 1, 64;" ::: "memory");
            for (int it = 0; it < nin; it++) {
                float a0=0.f,a1=0.f,a2=0.f,a3=0.f;
                const float* Mr = &sm.s.Ms[u*65];
                const float* zc = sm.s.zs[cur];
                #pragma unroll 16
                for (int c = 0; c < 64; c += 4) {
                    a0 += Mr[c]   * zc[c];
                    a1 += Mr[c+1] * zc[c+1];
                    a2 += Mr[c+2] * zc[c+2];
                    a3 += Mr[c+3] * zc[c+3];
                }
                float acc = (a0+a1) + (a2+a3);
                z = (r - lam2 * (acc - Muu * z)) * dinv;
                if (it + 1 < nin) {
                    sm.s.zs[cur^1][u] = z;
                    asm volatile("bar.sync 1, 64;" ::: "memory");
                    cur ^= 1;
                }
            }
            g_x[h*64 + u] = z;
        }
    };

    // ---------------- matvec: y = D x (all 128 CTAs, HBM-streaming) -----------
    auto matvec = [&]() {
        const float4* x4 = (const float4*)g_x;
        float4* xs4 = (float4*)sm.s.xs;
        for (int i = t; i < 1024; i += TPB) xs4[i] = x4[i];
        __syncthreads();
        int w = t >> 5, lane = t & 31;
        int row0 = cta * 32 + w * 2;
        #pragma unroll
        for (int rr = 0; rr < 2; rr++) {
            int row = row0 + rr;
            const float4* D4 = (const float4*)(D + (size_t)row * 4096);
            float acc = 0.0f;
            #pragma unroll
            for (int it = 0; it < 32; it++) {
                float4 d  = D4[lane + 32*it];
                float4 xv = xs4[lane + 32*it];
                acc += d.x*xv.x + d.y*xv.y + d.z*xv.z + d.w*xv.w;
            }
            #pragma unroll
            for (int off = 16; off > 0; off >>= 1)
                acc += __shfl_xor_sync(0xffffffffu, acc, off);
            if (lane == 0) g_y[row] = acc;
        }
        __syncthreads();
    };

    apply(0, NIN0);
    gbar();   // 2
    for (int it = 0; it < FPITERS; it++) {
        matvec();
        gbar();
        apply(1, NIN1);
        gbar();
    }

    // CTAs 8..127: all remaining work uses 8 CTAs; exit now.
    if (cta >= 8) return;

    // ================= Jacobi SVD on CTA0; CTAs 1-7 wait at gbar8 =============
    if (cta == 0) {
        float* Gf = sm.f.Gf;
        float4* Gc = (float4*)sm.f.Gf;
        float* nrm = sm.f.nrm;
        int lane = t & 31, w = t >> 5;

        for (int i = t; i < 4096; i += TPB) {
            int r = i >> 6, j = i & 63;
            Gf[j*68 + r] = g_x[i] + thP[i];
        }
        __syncthreads();
        if (t < 64) {
            float acc = 0.0f;
            #pragma unroll 16
            for (int r = 0; r < 64; r++) { float g = Gf[t*68 + r]; acc += g*g; }
            nrm[t] = acc;
        }
        __syncthreads();

        // 16 warps x 2 pairs (16-lane groups); lane kk owns float4 block kk.
        // Always rotate: branch-free round (dp guarded; |zeta|=inf -> identity).
        {
            int grp = lane >> 4;
            int kk  = lane & 15;
            int k   = (w << 1) | grp;            // pair id 0..31
            for (int sweep = 0; sweep < MAXSWEEP; sweep++) {
                int p, q;
                if (k == 0) { p = 63; q = 0; }
                else { p = k; q = 63 - k; }
                for (int r = 0; r < 63; r++) {
                    float4 gp = Gc[p*17 + kk];
                    float4 gq = Gc[q*17 + kk];
                    float dp = gp.x*gq.x + gp.y*gq.y + gp.z*gq.z + gp.w*gq.w;
                    #pragma unroll
                    for (int o = 8; o; o >>= 1) dp += __shfl_xor_sync(0xffffffffu, dp, o);
                    float npp = nrm[p], nqq = nrm[q];
                    float dpg = copysignf(fmaxf(fabsf(dp), 1e-30f), dp);
                    float zeta = __fdividef(nqq - npp, 2.0f * dpg);
                    float tt = copysignf(__fdividef(1.0f, fabsf(zeta) + __fsqrt_rn(1.0f + zeta*zeta)), zeta);
                    float c = __frsqrt_rn(1.0f + tt*tt), s = tt * c;
                    float4 a, b;
                    a.x = c*gp.x - s*gq.x;  b.x = s*gp.x + c*gq.x;
                    a.y = c*gp.y - s*gq.y;  b.y = s*gp.y + c*gq.y;
                    a.z = c*gp.z - s*gq.z;  b.z = s*gp.z + c*gq.z;
                    a.w = c*gp.w - s*gq.w;  b.w = s*gp.w + c*gq.w;
                    Gc[p*17 + kk] = a;
                    Gc[q*17 + kk] = b;
                    if (kk == 0) { nrm[p] = npp - tt*dpg; nrm[q] = nqq + tt*dpg; }
                    __syncthreads();
                    if (k == 0) { q = (q + 1 == 63) ? 0 : q + 1; }
                    else { p = (p + 1 == 63) ? 0 : p + 1; q = (q + 1 == 63) ? 0 : q + 1; }
                }
            }
        }

        // singular values + threshold + spectral factors
        if (t < 64) {
            float acc = 0.0f;
            #pragma unroll 16
            for (int r = 0; r < 64; r++) { float g = Gf[t*68 + r]; acc += g*g; }
            sm.f.sarr[t] = sqrtf(acc);
        }
        __syncthreads();
        if (t == 0) {
            float m = 0.0f;
            for (int j = 0; j < 64; j++) m = fmaxf(m, sm.f.sarr[j]);
            float vv = *vp;
            float tau = 0.4f / (1.0f + expf(-vv));
            sm.f.thr_s = tau * m;
        }
        __syncthreads();
        if (t < 64) {
            float s = sm.f.sarr[t];
            float st = s - sm.f.thr_s;
            g_sv[t] = s;
            g_fs[t] = (st > 0.0f) ? st / (s*s*s) : 0.0f;
        }
        // dump G row-major: gG[r*64 + j] = G[r][j]  (into dead g_StS)
        for (int i = t; i < 4096; i += TPB) {
            int r = i >> 6, j = i & 63;
            g_StS[i] = Gf[j*68 + r];
        }
    }
    gbar8();   // Jacobi results visible to CTAs 0-7

    // ======= parallel DK epilogue: Ltmp = G M G^T X, M = DK(w, N) =============
    float neta = *netap;
    int idx = cta * TPB + t;

    // Phase A: Y[i][c] = sum_r G[r][i] X[r][c]; N -> M
    {
        int i = idx >> 6, c = idx & 63;     // i uniform per warp -> broadcast
        float accY = 0.0f, accN = 0.0f;
        #pragma unroll 8
        for (int r = 0; r < 64; r++) {
            float gri = g_StS[r*64 + i];
            accY += gri * (g_x[r*64 + c] + thP[r*64 + c]);
            accN += gri * g_StS[r*64 + c];
        }
        g_y[idx] = accY;
        float Mv;
        if (i == c) Mv = g_fs[i];
        else {
            float si = g_sv[i], sj = g_sv[c];
            float ni = si*si, nj = sj*sj, dn = nj - ni;
            Mv = (fabsf(dn) > 1e-6f*(ni + nj) + 1e-30f)
                 ? accN * (g_fs[c] - g_fs[i]) / dn : 0.0f;
        }
        g_b[idx] = Mv;
    }
    gbar8();

    // Phase B: Z[i][c] = sum_m M[i][m] Y[m][c]
    {
        int i = idx >> 6, c = idx & 63;
        float acc = 0.0f;
        #pragma unroll 8
        for (int m = 0; m < 64; m++) acc += g_b[i*64 + m] * g_y[m*64 + c];
        g_qf[idx] = acc;
    }
    gbar8();

    // Phase C: Ltmp = G Z ; Ptmp = thP + neta*(x - Ltmp)
    {
        int r = idx >> 6, c = idx & 63;
        float acc = 0.0f;
        #pragma unroll 8
        for (int j = 0; j < 64; j++) acc += g_StS[r*64 + j] * g_qf[j*64 + c];
        out[idx]        = acc;
        out[4096 + idx] = thP[idx] + neta * (g_x[idx] - acc);
    }
}

// ---------------- launch ----------------
extern "C" void kernel_launch(void* const* d_in, const int* in_sizes, int n_in,
                              void* d_out, int out_size) {
    const float* inp  = (const float*)d_in[0];
    const float* L    = (const float*)d_in[1];
    const void*  mask = d_in[2];
    const float* D    = (const float*)d_in[3];
    const float* thP  = (const float*)d_in[4];
    const float* v    = (const float*)d_in[5];
    const float* neta = (const float*)d_in[6];
    const float* lam1 = (const float*)d_in[7];
    const float* lam2 = (const float*)d_in[8];
    const float* rho  = (const float*)d_in[9];
    const float* S    = (const float*)d_in[10];
    float* out = (float*)d_out;

    k_all<<<NCTA, TPB>>>(inp, L, mask, D, thP, v, neta, lam1, lam2, rho, S, out);
}